// round 1
// baseline (speedup 1.0000x reference)
#include <cuda_runtime.h>
#include <math.h>

// NaiveFourierKANLayer: y[b,j] = sum_{i,g} cos(x[b,i]*g)*W0[j,i,g] + sin(x[b,i]*g)*W1[j,i,g] + bias[j]
// B=1024, I=256, G=300, O=256.
// GEMM view: M=1024, N=256, K=2*I*G=153600. A generated on the fly via rotation
// recurrence (no MUFU in the hot path), B (coeffs, 157MB) streamed from HBM.

#define NB 1024
#define NI 256
#define NG 300
#define NO 256

#define BM 64          // batch rows per CTA
#define BN 32          // output cols per CTA
#define GK 20          // g-values per stage
#define KCH (2*GK)     // k-values per stage (cos/sin interleaved)
#define NCHUNK (NG/GK) // 15 stages per i

typedef unsigned long long u64;

// Packed dual-FMA: 2 fp32 FMAs per fma-pipe slot (sm_100+ f32x2 path).
__device__ __forceinline__ void ffma2(u64 &d, u64 a, u64 b) {
    asm volatile("fma.rn.f32x2 %0, %1, %2, %0;" : "+l"(d) : "l"(a), "l"(b));
}
__device__ __forceinline__ u64 bcast2(float v) {
    u64 r;
    unsigned int u = __float_as_uint(v);
    asm("mov.b64 %0, {%1, %1};" : "=l"(r) : "r"(u));
    return r;
}

__global__ void __launch_bounds__(256, 1)
fkan_kernel(const float* __restrict__ x,
            const float* __restrict__ fc,     // [2][O][I][G]
            const float* __restrict__ bias,   // [O]
            float* __restrict__ out)          // [B][O]
{
    // A: [k][row]  k = 2*(g-g0) + (0=cos,1=sin)
    __shared__ __align__(16) float As[KCH][BM];
    // B: [k][j]
    __shared__ __align__(16) float Bs[KCH][BN];

    const int tid = threadIdx.x;
    const int m0  = blockIdx.x * BM;
    const int n0  = blockIdx.y * BN;

    // --- A-generation mapping: 64 rows x 4 g-slots (stride-4 recurrence) ---
    const int grow  = tid & 63;
    const int gslot = tid >> 6;      // 0..3, handles g = gslot+1, gslot+5, ...

    // --- B-load mapping: 2 trig x 32 j x 4 g-lanes, 5 g each ---
    const int btt = tid >> 7;        // 0 = cos coeffs, 1 = sin coeffs
    const int bj  = (tid >> 2) & 31;
    const int bgq = tid & 3;

    // --- compute mapping: 16 col-groups x 16 row-pair-groups ---
    const int cg = tid & 15;         // cols {n0+2cg, n0+2cg+1}
    const int pg = tid >> 4;         // row pairs {2pg,2pg+1} and {2pg+32,2pg+33}

    u64 acc0 = 0ull, acc1 = 0ull, acc2 = 0ull, acc3 = 0ull;

    const float* xrow = x + (size_t)(m0 + grow) * NI;
    const float* bsrc = fc + ((size_t)(btt * NO + n0 + bj) * NI) * NG;

    for (int i = 0; i < NI; ++i) {
        // ---- init rotation state for this i ----
        const float t = xrow[i];
        float c1, s1;
        sincosf(t, &s1, &c1);              // accurate path, |t| small
        // advance to starting angle (gslot+1)*t
        float cc = c1, ss = s1;
        #pragma unroll 3
        for (int a = 0; a < gslot; ++a) {
            float nc = fmaf(cc, c1, -ss * s1);
            ss = fmaf(ss, c1, cc * s1);
            cc = nc;
        }
        // step rotation = angle 4t (exact double-angle from (c1,s1))
        const float c2 = fmaf(c1, c1, -s1 * s1);
        const float s2 = 2.f * s1 * c1;
        const float c4 = fmaf(c2, c2, -s2 * s2);
        const float s4 = 2.f * s2 * c2;

        const float* src_i = bsrc + (size_t)i * NG;

        for (int ch = 0; ch < NCHUNK; ++ch) {
            // ---- generate A tile: 5 (c,s) pairs per thread ----
            #pragma unroll
            for (int m = 0; m < 5; ++m) {
                const int gidx = gslot + 4 * m;
                As[2 * gidx][grow]     = cc;
                As[2 * gidx + 1][grow] = ss;
                float nc = fmaf(cc, c4, -ss * s4);
                ss = fmaf(ss, c4, cc * s4);
                cc = nc;
            }
            // ---- load B tile: 5 coeffs per thread ----
            #pragma unroll
            for (int m = 0; m < 5; ++m) {
                const int g = bgq + 4 * m;
                Bs[2 * g + btt][bj] = src_i[ch * GK + g];
            }
            __syncthreads();

            // ---- 64x32x40 FMA block, FFMA2-packed over row pairs ----
            #pragma unroll
            for (int k = 0; k < KCH; ++k) {
                const u64 a01 = *(const u64*)&As[k][2 * pg];        // rows 2pg,2pg+1
                const u64 a23 = *(const u64*)&As[k][2 * pg + 32];   // rows 2pg+32,+33
                const float2 bf = *(const float2*)&Bs[k][2 * cg];
                const u64 b0 = bcast2(bf.x);
                const u64 b1 = bcast2(bf.y);
                ffma2(acc0, a01, b0);
                ffma2(acc1, a01, b1);
                ffma2(acc2, a23, b0);
                ffma2(acc3, a23, b1);
            }
            __syncthreads();
        }
    }

    // ---- epilogue: unpack and add bias ----
    float2 v0, v1, v2, v3;
    v0 = *(float2*)&acc0; v1 = *(float2*)&acc1;
    v2 = *(float2*)&acc2; v3 = *(float2*)&acc3;

    const int r0 = m0 + 2 * pg;
    const int r2 = m0 + 2 * pg + 32;
    const int cA = n0 + 2 * cg;
    const int cB = cA + 1;
    const float bA = bias[cA];
    const float bB = bias[cB];

    out[(size_t)r0 * NO + cA]       = v0.x + bA;
    out[(size_t)(r0 + 1) * NO + cA] = v0.y + bA;
    out[(size_t)r0 * NO + cB]       = v1.x + bB;
    out[(size_t)(r0 + 1) * NO + cB] = v1.y + bB;
    out[(size_t)r2 * NO + cA]       = v2.x + bA;
    out[(size_t)(r2 + 1) * NO + cA] = v2.y + bA;
    out[(size_t)r2 * NO + cB]       = v3.x + bB;
    out[(size_t)(r2 + 1) * NO + cB] = v3.y + bB;
}

extern "C" void kernel_launch(void* const* d_in, const int* in_sizes, int n_in,
                              void* d_out, int out_size) {
    const float* x    = (const float*)d_in[0];
    const float* fc   = (const float*)d_in[1];
    const float* bias = (const float*)d_in[2];
    float* out        = (float*)d_out;

    dim3 grid(NB / BM, NO / BN);   // 16 x 8 = 128 CTAs, one wave on 148 SMs
    fkan_kernel<<<grid, 256>>>(x, fc, bias, out);
}